// round 13
// baseline (speedup 1.0000x reference)
#include <cuda_runtime.h>
#include <cuda_bf16.h>
#include <cstdint>

#define B_ 32
#define S_ 2048
#define D_ 1024
#define E_ 64
#define K_ 8
#define T_ 128       // N_TAGS
#define KSPLIT 4
#define KCHUNK 256   // K per split
#define KS 32        // k sub-chunk (bf16 elems) staged in smem
#define RSTR 40      // bf16 elems per smem row (80B: conflict-free, 16B aligned)
#define BM 32
#define AH_OFF 0
#define AL_OFF (BM * RSTR)            // 1280
#define BH_OFF (2 * BM * RSTR)        // 2560
#define BL_OFF (BH_OFF + 128 * RSTR)  // 7680
#define STG_ELE (BL_OFF + 128 * RSTR) // 12800 bf16 = 25600 B per stage

// Scratch (allocation-free rule: __device__ globals)
__device__ __nv_bfloat16 g_eh[B_ * E_ * D_];     // 4 MB pooled, bf16-hi
__device__ __nv_bfloat16 g_el[B_ * E_ * D_];     // 4 MB pooled, bf16-lo
__device__ __nv_bfloat16 g_wh[T_ * D_];          // fc_w bf16-hi [T][D]
__device__ __nv_bfloat16 g_wl[T_ * D_];          // fc_w bf16-lo [T][D]
__device__ float g_part[KSPLIT * B_ * E_ * T_];  // 4 MB k-split partials

// ---- helpers ----------------------------------------------------------------
__device__ __forceinline__ uint32_t pack_hi_lo(float a, float b,
                                               float& ra, float& rb) {
    __nv_bfloat16 ha = __float2bfloat16_rn(a);
    __nv_bfloat16 hb = __float2bfloat16_rn(b);
    ra = a - __bfloat162float(ha);
    rb = b - __bfloat162float(hb);
    uint16_t ua = *(uint16_t*)&ha, ub = *(uint16_t*)&hb;
    return (uint32_t)ua | ((uint32_t)ub << 16);
}
__device__ __forceinline__ uint32_t pack_bf2(float a, float b) {
    __nv_bfloat16 ha = __float2bfloat16_rn(a);
    __nv_bfloat16 hb = __float2bfloat16_rn(b);
    uint16_t ua = *(uint16_t*)&ha, ub = *(uint16_t*)&hb;
    return (uint32_t)ua | ((uint32_t)ub << 16);
}

__device__ __forceinline__ void ldsm4(uint32_t* r, uint32_t addr) {
    asm volatile("ldmatrix.sync.aligned.m8n8.x4.shared.b16 {%0,%1,%2,%3}, [%4];"
                 : "=r"(r[0]), "=r"(r[1]), "=r"(r[2]), "=r"(r[3]) : "r"(addr));
}
__device__ __forceinline__ void mma16(float* d, const uint32_t* a,
                                      uint32_t b0, uint32_t b1) {
    asm volatile(
        "mma.sync.aligned.m16n8k16.row.col.f32.bf16.bf16.f32 "
        "{%0,%1,%2,%3}, {%4,%5,%6,%7}, {%8,%9}, {%0,%1,%2,%3};"
        : "+f"(d[0]), "+f"(d[1]), "+f"(d[2]), "+f"(d[3])
        : "r"(a[0]), "r"(a[1]), "r"(a[2]), "r"(a[3]), "r"(b0), "r"(b1));
}
__device__ __forceinline__ void cp16(uint32_t dst, const void* src) {
    asm volatile("cp.async.cg.shared.global [%0], [%1], 16;"
                 :: "r"(dst), "l"(src) : "memory");
}

// ---------------------------------------------------------------------------
// Kernel P: gather + masked mean pool -> bf16 hi/lo split outputs.
// De-serialized gather (R12-proven). fc_w split spread evenly: every block
// handles 64 elements (threads 0..63) -- no straggler blocks.
// ---------------------------------------------------------------------------
__global__ __launch_bounds__(256) void pool_kernel(
    const float* __restrict__ hs,      // [B,S,D]
    const int*   __restrict__ idx,     // [B,E,K]
    const int*   __restrict__ counts,  // [B,E]
    const int*   __restrict__ nent,    // [B]
    const float* __restrict__ W)       // fc_w [T,D]
{
    int be = blockIdx.x;           // 0..2047
    int b  = be >> 6;
    int e  = be & 63;
    int t  = threadIdx.x;

    // fc_w hi/lo split: 64 elements per block, threads 0..63 (issued early,
    // independent of the gather chain)
    if (t < 64) {
        int i = blockIdx.x * 64 + t;
        float w = W[i];
        __nv_bfloat16 wh = __float2bfloat16_rn(w);
        g_wh[i] = wh;
        g_wl[i] = __float2bfloat16_rn(w - __bfloat162float(wh));
    }

    int cnt    = counts[be];
    int ne     = nent[b];
    int4 ia    = *(const int4*)(idx + be * K_);
    int4 ib    = *(const int4*)(idx + be * K_ + 4);
    bool active = (e < ne);

    int r[8] = {ia.x, ia.y, ia.z, ia.w, ib.x, ib.y, ib.z, ib.w};
    #pragma unroll
    for (int k = 1; k < K_; ++k)
        r[k] = (k < cnt) ? r[k] : r[0];   // clamp -> dup loads hit L1

    float4 acc = make_float4(0.f, 0.f, 0.f, 0.f);
    if (active) {
        const float* base = hs + (size_t)b * (S_ * D_) + t * 4;
        float4 v[8];
        #pragma unroll
        for (int k = 0; k < K_; ++k)      // 8 unconditional batched LDG.128
            v[k] = *(const float4*)(base + (size_t)r[k] * D_);
        float inv = 1.0f / (float)cnt;
        #pragma unroll
        for (int k = 0; k < K_; ++k) {
            float w = (k < cnt) ? inv : 0.f;
            acc.x = fmaf(v[k].x, w, acc.x);
            acc.y = fmaf(v[k].y, w, acc.y);
            acc.z = fmaf(v[k].z, w, acc.z);
            acc.w = fmaf(v[k].w, w, acc.w);
        }
    }

    float rx, ry, rz, rw;
    uint2 hv, lv;
    hv.x = pack_hi_lo(acc.x, acc.y, rx, ry);
    hv.y = pack_hi_lo(acc.z, acc.w, rz, rw);
    lv.x = pack_bf2(rx, ry);
    lv.y = pack_bf2(rz, rw);
    *(uint2*)(g_eh + (size_t)be * D_ + t * 4) = hv;
    *(uint2*)(g_el + (size_t)be * D_ + t * 4) = lv;
}

// ---------------------------------------------------------------------------
// Kernel B: bf16x3 split-K GEMM via mma.sync.m16n8k16 + ldmatrix + cp.async.
// grid = (64 m-tiles, 4 k-splits) = 256 CTAs (2/SM), 256 threads (8 warps).
// CTA tile: M32 x N128 x K256; warp tile m16 x n32; double-buffered k32.
// ---------------------------------------------------------------------------
__global__ __launch_bounds__(256, 2) void mma_gemm()
{
    extern __shared__ __nv_bfloat16 sm[];
    uint32_t smb;
    asm("{ .reg .u64 t; cvta.to.shared.u64 t, %1; cvt.u32.u64 %0, t; }"
        : "=r"(smb) : "l"(sm));

    int tid  = threadIdx.x;
    int lane = tid & 31;
    int warp = tid >> 5;
    int mi = warp >> 2;            // 0..1  -> m-sub (16 rows)
    int ni = warp & 3;             // 0..3  -> n-sub (32 cols)
    int mrow0 = blockIdx.x * BM;
    int split = blockIdx.y;
    int kbase = split * KCHUNK;

    // ldmatrix per-lane offsets (bf16 elems)
    int tile = lane >> 3;
    int tr   = lane & 7;
    int aoff = (mi * 16 + (tile & 1) * 8 + tr) * RSTR + (tile >> 1) * 8;
    int boff[2];
    #pragma unroll
    for (int n2 = 0; n2 < 2; ++n2)
        boff[n2] = (ni * 32 + n2 * 16 + (tile >> 1) * 8 + tr) * RSTR + (tile & 1) * 8;

    float acc[4][4];
    #pragma unroll
    for (int n = 0; n < 4; ++n)
        #pragma unroll
        for (int p = 0; p < 4; ++p) acc[n][p] = 0.f;

    auto issue = [&](int stg, int it) {
        int kc = kbase + it * KS;
        uint32_t sb = smb + (uint32_t)(stg * STG_ELE * 2);
        // A hi/lo: 2 arrays x 32 rows x 4 segs = 256, one per thread
        {
            int arr = tid >> 7;            // 0=hi, 1=lo
            int rem = tid & 127;
            int row = rem >> 2, q = rem & 3;
            size_t g = (size_t)(mrow0 + row) * D_ + kc + q * 8;
            const __nv_bfloat16* src = arr ? g_el : g_eh;
            int off = arr ? AL_OFF : AH_OFF;
            cp16(sb + (uint32_t)((off + row * RSTR + q * 8) * 2), src + g);
        }
        // B hi/lo: 128 rows x 4 segs = 512 each, two per thread per array
        #pragma unroll
        for (int j = 0; j < 2; ++j) {
            int i   = tid + j * 256;
            int row = i >> 2, q = i & 3;
            size_t g = (size_t)row * D_ + kc + q * 8;
            cp16(sb + (uint32_t)((BH_OFF + row * RSTR + q * 8) * 2), g_wh + g);
            cp16(sb + (uint32_t)((BL_OFF + row * RSTR + q * 8) * 2), g_wl + g);
        }
        asm volatile("cp.async.commit_group;" ::: "memory");
    };

    issue(0, 0);

    #pragma unroll 1
    for (int it = 0; it < KCHUNK / KS; ++it) {
        int s = it & 1;
        asm volatile("cp.async.wait_group 0;" ::: "memory");
        __syncthreads();
        if (it + 1 < KCHUNK / KS) issue((it + 1) & 1, it + 1);

        uint32_t sb = smb + (uint32_t)(s * STG_ELE * 2);

        #pragma unroll
        for (int ks = 0; ks < KS / 16; ++ks) {
            uint32_t aH[4], aL[4];
            ldsm4(aH, sb + (uint32_t)((AH_OFF + aoff + ks * 16) * 2));
            ldsm4(aL, sb + (uint32_t)((AL_OFF + aoff + ks * 16) * 2));
            #pragma unroll
            for (int n2 = 0; n2 < 2; ++n2) {
                uint32_t bH[4], bL[4];
                ldsm4(bH, sb + (uint32_t)((BH_OFF + boff[n2] + ks * 16) * 2));
                ldsm4(bL, sb + (uint32_t)((BL_OFF + boff[n2] + ks * 16) * 2));
                mma16(acc[n2 * 2 + 0], aH, bH[0], bH[1]);
                mma16(acc[n2 * 2 + 1], aH, bH[2], bH[3]);
                mma16(acc[n2 * 2 + 0], aL, bH[0], bH[1]);
                mma16(acc[n2 * 2 + 1], aL, bH[2], bH[3]);
                mma16(acc[n2 * 2 + 0], aH, bL[0], bL[1]);
                mma16(acc[n2 * 2 + 1], aH, bL[2], bL[3]);
            }
        }
        __syncthreads();
    }

    // epilogue: write partials
    float* op = g_part + (size_t)split * (B_ * E_ * T_);
    int r0 = mrow0 + mi * 16 + (lane >> 2);
    #pragma unroll
    for (int nt = 0; nt < 4; ++nt) {
        int c = ni * 32 + nt * 8 + (lane & 3) * 2;
        float2 v0 = make_float2(acc[nt][0], acc[nt][1]);
        float2 v1 = make_float2(acc[nt][2], acc[nt][3]);
        *(float2*)(op + (size_t)r0 * T_ + c)       = v0;
        *(float2*)(op + (size_t)(r0 + 8) * T_ + c) = v1;
    }
}

// ---------------------------------------------------------------------------
// Kernel R: reduce 4 partials + bias -> out.
// ---------------------------------------------------------------------------
__global__ __launch_bounds__(256) void reduce_kernel(
    const float* __restrict__ bias, float* __restrict__ out)
{
    int i = blockIdx.x * 256 + threadIdx.x;   // 0 .. 262143
    float s = bias[i & (T_ - 1)];
    #pragma unroll
    for (int sp = 0; sp < KSPLIT; ++sp)
        s += g_part[(size_t)sp * (B_ * E_ * T_) + i];
    out[i] = s;
}

// ---------------------------------------------------------------------------
extern "C" void kernel_launch(void* const* d_in, const int* in_sizes, int n_in,
                              void* d_out, int out_size)
{
    const float* hs     = (const float*)d_in[0];
    const int*   idx    = (const int*)  d_in[1];
    const int*   counts = (const int*)  d_in[2];
    const int*   nent   = (const int*)  d_in[3];
    const float* fcw    = (const float*)d_in[4];
    const float* fcb    = (const float*)d_in[5];
    float*       out    = (float*)d_out;

    const int smem_bytes = 2 * STG_ELE * 2;   // 51200
    cudaFuncSetAttribute(mma_gemm, cudaFuncAttributeMaxDynamicSharedMemorySize,
                         smem_bytes);

    pool_kernel<<<B_ * E_, 256>>>(hs, idx, counts, nent, fcw);
    mma_gemm<<<dim3(B_ * E_ / BM, KSPLIT), 256, smem_bytes>>>();
    reduce_kernel<<<(B_ * E_ * T_) / 256, 256>>>(fcb, out);
}

// round 14
// speedup vs baseline: 1.4443x; 1.4443x over previous
#include <cuda_runtime.h>
#include <cuda_bf16.h>
#include <cstdint>

#define B_ 32
#define S_ 2048
#define D_ 1024
#define E_ 64
#define K_ 8
#define T_ 128       // N_TAGS
#define KSPLIT 4
#define KCHUNK 256   // K per split
#define KS 32        // k sub-chunk (bf16 elems) staged in smem
#define RSTR 40      // bf16 elems per smem row (80B: conflict-free, 16B aligned)
#define AH_OFF 0
#define AL_OFF (64 * RSTR)          // 2560
#define BH_OFF (2 * 64 * RSTR)      // 5120
#define BL_OFF (BH_OFF + 128 * RSTR) // 10240
#define STG_ELE (BL_OFF + 128 * RSTR) // 15360 bf16 = 30720 B per stage

// Scratch (allocation-free rule: __device__ globals)
__device__ __nv_bfloat16 g_eh[B_ * E_ * D_];     // 4 MB pooled, bf16-hi
__device__ __nv_bfloat16 g_el[B_ * E_ * D_];     // 4 MB pooled, bf16-lo
__device__ __nv_bfloat16 g_wh[T_ * D_];          // fc_w bf16-hi [T][D]
__device__ __nv_bfloat16 g_wl[T_ * D_];          // fc_w bf16-lo [T][D]
__device__ float g_part[KSPLIT * B_ * E_ * T_];  // 4 MB k-split partials

// ---- helpers ----------------------------------------------------------------
__device__ __forceinline__ uint32_t pack_hi_lo(float a, float b,
                                               float& ra, float& rb) {
    __nv_bfloat16 ha = __float2bfloat16_rn(a);
    __nv_bfloat16 hb = __float2bfloat16_rn(b);
    ra = a - __bfloat162float(ha);
    rb = b - __bfloat162float(hb);
    uint16_t ua = *(uint16_t*)&ha, ub = *(uint16_t*)&hb;
    return (uint32_t)ua | ((uint32_t)ub << 16);
}
__device__ __forceinline__ uint32_t pack_bf2(float a, float b) {
    __nv_bfloat16 ha = __float2bfloat16_rn(a);
    __nv_bfloat16 hb = __float2bfloat16_rn(b);
    uint16_t ua = *(uint16_t*)&ha, ub = *(uint16_t*)&hb;
    return (uint32_t)ua | ((uint32_t)ub << 16);
}

__device__ __forceinline__ void ldsm4(uint32_t* r, uint32_t addr) {
    asm volatile("ldmatrix.sync.aligned.m8n8.x4.shared.b16 {%0,%1,%2,%3}, [%4];"
                 : "=r"(r[0]), "=r"(r[1]), "=r"(r[2]), "=r"(r[3]) : "r"(addr));
}
__device__ __forceinline__ void mma16(float* d, const uint32_t* a,
                                      uint32_t b0, uint32_t b1) {
    asm volatile(
        "mma.sync.aligned.m16n8k16.row.col.f32.bf16.bf16.f32 "
        "{%0,%1,%2,%3}, {%4,%5,%6,%7}, {%8,%9}, {%0,%1,%2,%3};"
        : "+f"(d[0]), "+f"(d[1]), "+f"(d[2]), "+f"(d[3])
        : "r"(a[0]), "r"(a[1]), "r"(a[2]), "r"(a[3]), "r"(b0), "r"(b1));
}
__device__ __forceinline__ void cp16(uint32_t dst, const void* src) {
    asm volatile("cp.async.cg.shared.global [%0], [%1], 16;"
                 :: "r"(dst), "l"(src) : "memory");
}

// ---------------------------------------------------------------------------
// Kernel P: gather + masked mean pool -> bf16 hi/lo split outputs.
// R12-proven form: de-serialized gather (MLP=8), W split in blocks < 512.
// ---------------------------------------------------------------------------
__global__ __launch_bounds__(256) void pool_kernel(
    const float* __restrict__ hs,      // [B,S,D]
    const int*   __restrict__ idx,     // [B,E,K]
    const int*   __restrict__ counts,  // [B,E]
    const int*   __restrict__ nent,    // [B]
    const float* __restrict__ W)       // fc_w [T,D]
{
    int be = blockIdx.x;           // 0..2047
    int b  = be >> 6;
    int e  = be & 63;
    int t  = threadIdx.x;

    // independent loads: issue all three streams up front
    int cnt    = counts[be];
    int ne     = nent[b];
    int4 ia    = *(const int4*)(idx + be * K_);
    int4 ib    = *(const int4*)(idx + be * K_ + 4);
    bool active = (e < ne);

    int r[8] = {ia.x, ia.y, ia.z, ia.w, ib.x, ib.y, ib.z, ib.w};
    #pragma unroll
    for (int k = 1; k < K_; ++k)
        r[k] = (k < cnt) ? r[k] : r[0];   // clamp -> dup loads hit L1

    float4 acc = make_float4(0.f, 0.f, 0.f, 0.f);
    if (active) {
        const float* base = hs + (size_t)b * (S_ * D_) + t * 4;
        float4 v[8];
        #pragma unroll
        for (int k = 0; k < K_; ++k)      // 8 unconditional batched LDG.128
            v[k] = *(const float4*)(base + (size_t)r[k] * D_);
        float inv = 1.0f / (float)cnt;
        #pragma unroll
        for (int k = 0; k < K_; ++k) {
            float w = (k < cnt) ? inv : 0.f;
            acc.x = fmaf(v[k].x, w, acc.x);
            acc.y = fmaf(v[k].y, w, acc.y);
            acc.z = fmaf(v[k].z, w, acc.z);
            acc.w = fmaf(v[k].w, w, acc.w);
        }
    }

    float rx, ry, rz, rw;
    uint2 hv, lv;
    hv.x = pack_hi_lo(acc.x, acc.y, rx, ry);
    hv.y = pack_hi_lo(acc.z, acc.w, rz, rw);
    lv.x = pack_bf2(rx, ry);
    lv.y = pack_bf2(rz, rw);
    *(uint2*)(g_eh + (size_t)be * D_ + t * 4) = hv;
    *(uint2*)(g_el + (size_t)be * D_ + t * 4) = lv;

    // fc_w hi/lo split: 512 blocks x 256 elements
    if (blockIdx.x < (T_ * D_) / 256) {
        int i = blockIdx.x * 256 + t;
        float w = W[i];
        __nv_bfloat16 wh = __float2bfloat16_rn(w);
        g_wh[i] = wh;
        g_wl[i] = __float2bfloat16_rn(w - __bfloat162float(wh));
    }
}

// ---------------------------------------------------------------------------
// Kernel B: bf16x3 split-K GEMM via mma.sync.m16n8k16 + ldmatrix + cp.async.
// grid = (32 m-tiles, 4 k-splits) = 128 CTAs (~1/SM), 256 threads (8 warps).
// CTA tile: M64 x N128 x K256; warp tile m32 x n32; double-buffered k32.
// ---------------------------------------------------------------------------
__global__ __launch_bounds__(256, 2) void mma_gemm()
{
    extern __shared__ __nv_bfloat16 sm[];
    uint32_t smb;
    asm("{ .reg .u64 t; cvta.to.shared.u64 t, %1; cvt.u32.u64 %0, t; }"
        : "=r"(smb) : "l"(sm));

    int tid  = threadIdx.x;
    int lane = tid & 31;
    int warp = tid >> 5;
    int mi = warp >> 2;            // 0..1  -> m-sub (32 rows)
    int ni = warp & 3;             // 0..3  -> n-sub (32 cols)
    int mrow0 = blockIdx.x * 64;
    int split = blockIdx.y;
    int kbase = split * KCHUNK;

    // ldmatrix per-lane offsets (bf16 elems)
    int tile = lane >> 3;
    int tr   = lane & 7;
    int aoff[2], boff[2];
    #pragma unroll
    for (int f = 0; f < 2; ++f)
        aoff[f] = (mi * 32 + f * 16 + (tile & 1) * 8 + tr) * RSTR + (tile >> 1) * 8;
    #pragma unroll
    for (int n2 = 0; n2 < 2; ++n2)
        boff[n2] = (ni * 32 + n2 * 16 + (tile >> 1) * 8 + tr) * RSTR + (tile & 1) * 8;

    float acc[2][4][4];
    #pragma unroll
    for (int f = 0; f < 2; ++f)
        #pragma unroll
        for (int n = 0; n < 4; ++n)
            #pragma unroll
            for (int p = 0; p < 4; ++p) acc[f][n][p] = 0.f;

    auto issue = [&](int stg, int it) {
        int kc = kbase + it * KS;
        uint32_t sb = smb + (uint32_t)(stg * STG_ELE * 2);
        {
            int row = tid >> 2, q = tid & 3;
            size_t g = (size_t)(mrow0 + row) * D_ + kc + q * 8;
            cp16(sb + (uint32_t)((AH_OFF + row * RSTR + q * 8) * 2), g_eh + g);
            cp16(sb + (uint32_t)((AL_OFF + row * RSTR + q * 8) * 2), g_el + g);
        }
        #pragma unroll
        for (int j = 0; j < 2; ++j) {
            int i   = tid + j * 256;
            int row = i >> 2, q = i & 3;
            size_t g = (size_t)row * D_ + kc + q * 8;
            cp16(sb + (uint32_t)((BH_OFF + row * RSTR + q * 8) * 2), g_wh + g);
            cp16(sb + (uint32_t)((BL_OFF + row * RSTR + q * 8) * 2), g_wl + g);
        }
        asm volatile("cp.async.commit_group;" ::: "memory");
    };

    issue(0, 0);

    #pragma unroll 1
    for (int it = 0; it < KCHUNK / KS; ++it) {
        int s = it & 1;
        asm volatile("cp.async.wait_group 0;" ::: "memory");
        __syncthreads();
        if (it + 1 < KCHUNK / KS) issue((it + 1) & 1, it + 1);

        uint32_t sb = smb + (uint32_t)(s * STG_ELE * 2);

        #pragma unroll
        for (int ks = 0; ks < KS / 16; ++ks) {
            uint32_t aH[2][4], aL[2][4];
            #pragma unroll
            for (int f = 0; f < 2; ++f) {
                ldsm4(aH[f], sb + (uint32_t)((AH_OFF + aoff[f] + ks * 16) * 2));
                ldsm4(aL[f], sb + (uint32_t)((AL_OFF + aoff[f] + ks * 16) * 2));
            }
            #pragma unroll
            for (int n2 = 0; n2 < 2; ++n2) {
                uint32_t bH[4], bL[4];
                ldsm4(bH, sb + (uint32_t)((BH_OFF + boff[n2] + ks * 16) * 2));
                ldsm4(bL, sb + (uint32_t)((BL_OFF + boff[n2] + ks * 16) * 2));
                #pragma unroll
                for (int f = 0; f < 2; ++f) {
                    mma16(acc[f][n2 * 2 + 0], aH[f], bH[0], bH[1]);
                    mma16(acc[f][n2 * 2 + 1], aH[f], bH[2], bH[3]);
                    mma16(acc[f][n2 * 2 + 0], aL[f], bH[0], bH[1]);
                    mma16(acc[f][n2 * 2 + 1], aL[f], bH[2], bH[3]);
                    mma16(acc[f][n2 * 2 + 0], aH[f], bL[0], bL[1]);
                    mma16(acc[f][n2 * 2 + 1], aH[f], bL[2], bL[3]);
                }
            }
        }
        __syncthreads();
    }

    // epilogue: write partials
    float* op = g_part + (size_t)split * (B_ * E_ * T_);
    #pragma unroll
    for (int f = 0; f < 2; ++f) {
        int r0 = mrow0 + mi * 32 + f * 16 + (lane >> 2);
        #pragma unroll
        for (int nt = 0; nt < 4; ++nt) {
            int c = ni * 32 + nt * 8 + (lane & 3) * 2;
            float2 v0 = make_float2(acc[f][nt][0], acc[f][nt][1]);
            float2 v1 = make_float2(acc[f][nt][2], acc[f][nt][3]);
            *(float2*)(op + (size_t)r0 * T_ + c)       = v0;
            *(float2*)(op + (size_t)(r0 + 8) * T_ + c) = v1;
        }
    }
}

// ---------------------------------------------------------------------------
// Kernel R: reduce 4 partials + bias -> out.
// ---------------------------------------------------------------------------
__global__ __launch_bounds__(256) void reduce_kernel(
    const float* __restrict__ bias, float* __restrict__ out)
{
    int i = blockIdx.x * 256 + threadIdx.x;   // 0 .. 262143
    float s = bias[i & (T_ - 1)];
    #pragma unroll
    for (int sp = 0; sp < KSPLIT; ++sp)
        s += g_part[(size_t)sp * (B_ * E_ * T_) + i];
    out[i] = s;
}

// ---------------------------------------------------------------------------
extern "C" void kernel_launch(void* const* d_in, const int* in_sizes, int n_in,
                              void* d_out, int out_size)
{
    const float* hs     = (const float*)d_in[0];
    const int*   idx    = (const int*)  d_in[1];
    const int*   counts = (const int*)  d_in[2];
    const int*   nent   = (const int*)  d_in[3];
    const float* fcw    = (const float*)d_in[4];
    const float* fcb    = (const float*)d_in[5];
    float*       out    = (float*)d_out;

    const int smem_bytes = 2 * STG_ELE * 2;   // 61440
    cudaFuncSetAttribute(mma_gemm, cudaFuncAttributeMaxDynamicSharedMemorySize,
                         smem_bytes);

    pool_kernel<<<B_ * E_, 256>>>(hs, idx, counts, nent, fcw);
    mma_gemm<<<dim3(B_ * E_ / 64, KSPLIT), 256, smem_bytes>>>();
    reduce_kernel<<<(B_ * E_ * T_) / 256, 256>>>(fcb, out);
}